// round 1
// baseline (speedup 1.0000x reference)
#include <cuda_runtime.h>
#include <math.h>

#define Bb 32
#define Nn 128
#define Dd 64
#define Ee 5
#define T_ITERS 6

// scratch (allocation-free rule: __device__ globals)
__device__ float g_msg[Bb*Nn*Ee*Dd];      // 5.24 MB
__device__ float g_row[Bb*Nn*Ee];
__device__ float g_col[Bb*Nn*Ee];
__device__ float g_merged[Bb*Nn*Dd];      // 1 MB
__device__ float g_prop[Bb*Nn*Dd];        // 1 MB

// ---------------------------------------------------------------------------
// Kernel 1: msg[b,n,e,f] = sum_d prop[b,n,d]*We[e,d,f] + be[e,f]
//           row[b,n,e]   = sum_f msg * Wa[e, f]
//           col[b,n,e]   = sum_f msg * Wa[e, D+f]
// grid: B*(N/8) = 512 blocks, 320 threads (t = e*64+f)
// ---------------------------------------------------------------------------
__global__ void k_msg(const float* __restrict__ prop_ext,
                      const float* __restrict__ We,
                      const float* __restrict__ be,
                      const float* __restrict__ Wa) {
    const int NT = 8;
    const float* prop = prop_ext ? prop_ext : g_prop;

    int blk = blockIdx.x;
    int b   = blk / (Nn / NT);
    int n0  = (blk % (Nn / NT)) * NT;
    int t   = threadIdx.x;            // 0..319
    int e   = t / Dd;
    int f   = t % Dd;

    __shared__ float sp[NT][Dd];          // prop rows
    __shared__ float smsg[NT][Ee * Dd];   // msg tile for row/col reduction

    for (int idx = t; idx < NT * Dd; idx += 320) {
        int nn = idx / Dd, d = idx % Dd;
        sp[nn][d] = prop[(size_t)(b * Nn + n0 + nn) * Dd + d];
    }
    __syncthreads();

    float acc[NT];
    float bev = be[e * Dd + f];
#pragma unroll
    for (int nn = 0; nn < NT; nn++) acc[nn] = bev;

    const float* Wecol = We + e * Dd * Dd + f;   // stride D over d
#pragma unroll 8
    for (int d = 0; d < Dd; d++) {
        float w = Wecol[d * Dd];
#pragma unroll
        for (int nn = 0; nn < NT; nn++) acc[nn] += sp[nn][d] * w;
    }

#pragma unroll
    for (int nn = 0; nn < NT; nn++) {
        g_msg[((size_t)(b * Nn + n0 + nn) * Ee + e) * Dd + f] = acc[nn];
        smsg[nn][e * Dd + f] = acc[nn];
    }
    __syncthreads();

    // row/col reductions: 8 nodes * 5 experts * 2 = 80 threads do it
    if (t < NT * Ee * 2) {
        int nn    = t / (Ee * 2);
        int rest  = t % (Ee * 2);
        int ee    = rest / 2;
        int iscol = rest & 1;
        const float* wa = Wa + ee * 2 * Dd + iscol * Dd;
        float s = 0.f;
#pragma unroll 8
        for (int ff = 0; ff < Dd; ff++) s += smsg[nn][ee * Dd + ff] * wa[ff];
        if (iscol) g_col[(b * Nn + n0 + nn) * Ee + ee] = s;
        else       g_row[(b * Nn + n0 + nn) * Ee + ee] = s;
    }
}

// ---------------------------------------------------------------------------
// Kernel 2: scores[b,i,j,e] = sigmoid(row[i,e]+col[j,e]+ba[e]) * mask[b,i,j]
//           -> streamed to out[t,b,i,j,e]
//           merged[b,i,d] = sum_{j,e} scores * msg[b,j,e,d]
// grid: B*(N/16) = 256 blocks, 256 threads
// thread: d = tid%64, grp = tid/64 -> rows i = grp*4 + q (q=0..3)
// ---------------------------------------------------------------------------
__global__ void k_scores_merge(int titer,
                               const int* __restrict__ mask,
                               const float* __restrict__ ba,
                               float* __restrict__ out) {
    const int TI = 16, TJ = 16;
    int blk = blockIdx.x;
    int b   = blk / (Nn / TI);
    int i0  = (blk % (Nn / TI)) * TI;
    int tid = threadIdx.x;
    int d   = tid % Dd;
    int grp = tid / Dd;   // 0..3

    __shared__ float srow[TI][Ee];
    __shared__ float sba[Ee];
    __shared__ float smsg[TJ][Ee * Dd];   // 20 KB
    __shared__ float scol[TJ][Ee];
    __shared__ float ssc[TI][TJ][Ee];     // 5 KB
    __shared__ float smask[TI][TJ];

    if (tid < Ee) sba[tid] = ba[tid];
    for (int idx = tid; idx < TI * Ee; idx += 256) {
        int i = idx / Ee, e = idx % Ee;
        srow[i][e] = g_row[(b * Nn + i0 + i) * Ee + e];
    }

    float acc[4] = {0.f, 0.f, 0.f, 0.f};

    for (int j0 = 0; j0 < Nn; j0 += TJ) {
        __syncthreads();   // protect smsg/ssc from prior iter readers

        for (int idx = tid; idx < TJ * Ee * Dd; idx += 256) {
            int j = idx / (Ee * Dd), c = idx % (Ee * Dd);
            smsg[j][c] = g_msg[(size_t)(b * Nn + j0 + j) * (Ee * Dd) + c];
        }
        for (int idx = tid; idx < TJ * Ee; idx += 256) {
            int j = idx / Ee, e = idx % Ee;
            scol[j][e] = g_col[(b * Nn + j0 + j) * Ee + e];
        }
        for (int idx = tid; idx < TI * TJ; idx += 256) {
            int i = idx / TJ, j = idx % TJ;
            smask[i][j] = (float)mask[(size_t)(b * Nn + i0 + i) * Nn + j0 + j];
        }
        __syncthreads();

        // scores: compute, stash to smem, stream to out
        for (int idx = tid; idx < TI * TJ * Ee; idx += 256) {
            int i = idx / (TJ * Ee);
            int j = (idx / Ee) % TJ;
            int e = idx % Ee;
            float x = srow[i][e] + scol[j][e] + sba[e];
            float s = (1.f / (1.f + __expf(-x))) * smask[i][j];
            ssc[i][j][e] = s;
            out[(((((size_t)titer * Bb + b) * Nn + i0 + i) * Nn + j0 + j) * Ee) + e] = s;
        }
        __syncthreads();

        // merged accumulation (GEMM fragment): 16j * 5e = 80 FMA per row per tile
#pragma unroll
        for (int q = 0; q < 4; q++) {
            int i = grp * 4 + q;
            float a = acc[q];
#pragma unroll 4
            for (int j = 0; j < TJ; j++) {
#pragma unroll
                for (int e = 0; e < Ee; e++) {
                    a += ssc[i][j][e] * smsg[j][e * Dd + d];
                }
            }
            acc[q] = a;
        }
    }

#pragma unroll
    for (int q = 0; q < 4; q++) {
        int i = grp * 4 + q;
        g_merged[(size_t)(b * Nn + i0 + i) * Dd + d] = acc[q];
    }
}

// ---------------------------------------------------------------------------
// Kernel 3: GRU update
//   a  = [merged, prop]            (128)
//   r  = sigmoid(a @ Wr + br)      z = sigmoid(a @ Wz + bz)
//   h~ = tanh([merged, r*prop] @ Wh + bh)
//   prop' = (1-z)*prop + z*h~
// grid: B*N/16 = 256 blocks, 256 threads (d = tid%64, rows = grp*4+q)
// ---------------------------------------------------------------------------
__global__ void k_gru(const float* __restrict__ prop_ext,
                      const float* __restrict__ Wr, const float* __restrict__ br,
                      const float* __restrict__ Wz, const float* __restrict__ bz,
                      const float* __restrict__ Wh, const float* __restrict__ bh) {
    const int NT = 16;
    const float* prop = prop_ext ? prop_ext : g_prop;

    int r0  = blockIdx.x * NT;   // global (b*N+n) row base
    int tid = threadIdx.x;
    int d   = tid % Dd;
    int grp = tid / Dd;          // 0..3

    __shared__ float sa[NT][2 * Dd];   // [merged | prop]
    __shared__ float sh2[NT][Dd];      // r * prop

    for (int idx = tid; idx < NT * Dd; idx += 256) {
        int rr = idx / Dd, dd = idx % Dd;
        sa[rr][dd]      = g_merged[(size_t)(r0 + rr) * Dd + dd];
        sa[rr][Dd + dd] = prop[(size_t)(r0 + rr) * Dd + dd];
    }
    __syncthreads();

    float accr[4], accz[4];
    float brv = br[d], bzv = bz[d];
#pragma unroll
    for (int q = 0; q < 4; q++) { accr[q] = brv; accz[q] = bzv; }

#pragma unroll 4
    for (int k = 0; k < 2 * Dd; k++) {
        float wr = Wr[k * Dd + d];
        float wz = Wz[k * Dd + d];
#pragma unroll
        for (int q = 0; q < 4; q++) {
            float av = sa[grp * 4 + q][k];
            accr[q] += av * wr;
            accz[q] += av * wz;
        }
    }

    float zv[4];
#pragma unroll
    for (int q = 0; q < 4; q++) {
        int rr = grp * 4 + q;
        float rg = 1.f / (1.f + __expf(-accr[q]));
        zv[q]    = 1.f / (1.f + __expf(-accz[q]));
        sh2[rr][d] = rg * sa[rr][Dd + d];
    }
    __syncthreads();

    float acch[4];
    float bhv = bh[d];
#pragma unroll
    for (int q = 0; q < 4; q++) acch[q] = bhv;

#pragma unroll 4
    for (int k = 0; k < Dd; k++) {
        float wh = Wh[k * Dd + d];
#pragma unroll
        for (int q = 0; q < 4; q++) acch[q] += sa[grp * 4 + q][k] * wh;
    }
#pragma unroll 4
    for (int k = 0; k < Dd; k++) {
        float wh = Wh[(Dd + k) * Dd + d];
#pragma unroll
        for (int q = 0; q < 4; q++) acch[q] += sh2[grp * 4 + q][k] * wh;
    }

#pragma unroll
    for (int q = 0; q < 4; q++) {
        int rr = grp * 4 + q;
        float h  = tanhf(acch[q]);
        float pv = sa[rr][Dd + d];
        g_prop[(size_t)(r0 + rr) * Dd + d] = (1.f - zv[q]) * pv + zv[q] * h;
    }
}

// ---------------------------------------------------------------------------
extern "C" void kernel_launch(void* const* d_in, const int* in_sizes, int n_in,
                              void* d_out, int out_size) {
    const float* inputs = (const float*)d_in[0];
    const int*   mask   = (const int*)  d_in[1];
    const float* We     = (const float*)d_in[2];
    const float* be     = (const float*)d_in[3];
    const float* Wa     = (const float*)d_in[4];
    const float* ba     = (const float*)d_in[5];
    const float* Wr     = (const float*)d_in[6];
    const float* br     = (const float*)d_in[7];
    const float* Wz     = (const float*)d_in[8];
    const float* bz     = (const float*)d_in[9];
    const float* Wh     = (const float*)d_in[10];
    const float* bh     = (const float*)d_in[11];
    float* out = (float*)d_out;

    for (int t = 0; t < T_ITERS; t++) {
        const float* prop_src = (t == 0) ? inputs : nullptr;  // nullptr -> g_prop
        k_msg<<<Bb * (Nn / 8), 320>>>(prop_src, We, be, Wa);
        k_scores_merge<<<Bb * (Nn / 16), 256>>>(t, mask, ba, out);
        if (t != T_ITERS - 1) {
            k_gru<<<Bb * (Nn / 16), 256>>>(prop_src, Wr, br, Wz, bz, Wh, bh);
        }
    }
}

// round 2
// speedup vs baseline: 1.4343x; 1.4343x over previous
#include <cuda_runtime.h>
#include <math.h>

#define Bb 32
#define Nn 128
#define Dd 64
#define Ee 5
#define T_ITERS 6
#define JS 4
#define JT (Nn/JS)   // 32

__device__ float g_msg[Bb*Nn*Ee*Dd];
__device__ float g_row[Bb*Nn*Ee];
__device__ float g_col[Bb*Nn*Ee];
__device__ float g_part[JS][Bb*Nn][Dd];
__device__ float g_prop[Bb*Nn*Dd];

typedef unsigned long long u64;

__device__ __forceinline__ u64 pack2(float a, float b) {
    u64 r; asm("mov.b64 %0, {%1,%2};" : "=l"(r) : "f"(a), "f"(b)); return r;
}
__device__ __forceinline__ void unpack2(u64 v, float& a, float& b) {
    float x, y; asm("mov.b64 {%0,%1}, %2;" : "=f"(x), "=f"(y) : "l"(v));
    a = x; b = y;
}
__device__ __forceinline__ u64 fma2(u64 a, u64 b, u64 c) {
    u64 d; asm("fma.rn.f32x2 %0, %1, %2, %3;" : "=l"(d) : "l"(a), "l"(b), "l"(c)); return d;
}

// MUFU-free sigmoid: 2^y via round trick + deg-5 poly; 1/(1+t) via bit-trick + Newton.
__device__ __forceinline__ float fast_sigmoid(float x) {
    float y = -x * 1.4426950408889634f;          // log2(e)
    y = fminf(fmaxf(y, -126.f), 126.f);
    float fk = y + 12582912.f;                   // 1.5*2^23 round-to-int trick
    int   k  = __float_as_int(fk) - 0x4B400000;
    float f  = y - (fk - 12582912.f);            // f in [-0.5, 0.5]
    float p = 1.33336624e-3f;                    // 2^f Taylor (ln2^n / n!)
    p = fmaf(p, f, 9.61812910e-3f);
    p = fmaf(p, f, 5.55041087e-2f);
    p = fmaf(p, f, 2.40226507e-1f);
    p = fmaf(p, f, 6.93147182e-1f);
    p = fmaf(p, f, 1.0f);
    float t = __int_as_float(__float_as_int(p) + (k << 23));   // 2^y = exp(-x)
    float d = 1.0f + t;
    float r = __int_as_float(0x7EF311C3 - __float_as_int(d));  // ~1/d seed
    r = r * fmaf(-d, r, 2.0f);
    r = r * fmaf(-d, r, 2.0f);
    r = r * fmaf(-d, r, 2.0f);
    return r;
}
__device__ __forceinline__ float fast_tanh(float x) {
    return fmaf(2.f, fast_sigmoid(2.f * x), -1.f);
}

// ---------------------------------------------------------------------------
// k_msg: msg = prop @ We[e] + be ; row/col = msg . Wa
// grid 128 (b x 4 node-tiles of 32), 640 threads.
// thread: (e, f0..f0+3) x 4 nodes, register-tiled, packed FMA.
// ---------------------------------------------------------------------------
__global__ void k_msg(const float* __restrict__ prop_ext,
                      const float* __restrict__ We,
                      const float* __restrict__ be,
                      const float* __restrict__ Wa) {
    extern __shared__ float sm[];
    float* sp   = sm;            // [32][64]
    float* smsg = sm + 32*64;    // [32][320]
    const float* prop = prop_ext ? prop_ext : g_prop;

    int b  = blockIdx.x >> 2;
    int n0 = (blockIdx.x & 3) * 32;
    int t  = threadIdx.x;
    int ef4 = t % 80;
    int ng  = t / 80;             // 0..7
    int e   = ef4 >> 4;
    int f0  = (ef4 & 15) << 2;

    for (int idx = t; idx < 32*64; idx += 640)
        sp[idx] = prop[(size_t)(b*Nn + n0)*Dd + idx];
    __syncthreads();

    float4 bev = *(const float4*)&be[e*Dd + f0];
    u64 acc[4][2];
#pragma unroll
    for (int q = 0; q < 4; q++) {
        acc[q][0] = pack2(bev.x, bev.y);
        acc[q][1] = pack2(bev.z, bev.w);
    }

    const float4* We4 = (const float4*)(We + e*Dd*Dd + f0);
#pragma unroll 4
    for (int d = 0; d < Dd; d++) {
        float4 w = We4[d*16];
        u64 w01 = pack2(w.x, w.y), w23 = pack2(w.z, w.w);
#pragma unroll
        for (int q = 0; q < 4; q++) {
            float pv = sp[(ng*4+q)*Dd + d];
            u64 pp = pack2(pv, pv);
            acc[q][0] = fma2(pp, w01, acc[q][0]);
            acc[q][1] = fma2(pp, w23, acc[q][1]);
        }
    }
#pragma unroll
    for (int q = 0; q < 4; q++) {
        int n = ng*4+q;
        float4 v;
        unpack2(acc[q][0], v.x, v.y);
        unpack2(acc[q][1], v.z, v.w);
        *(float4*)&smsg[n*320 + e*64 + f0] = v;
        *(float4*)&g_msg[((size_t)(b*Nn + n0 + n))*320 + e*64 + f0] = v;
    }
    __syncthreads();

    if (t < 320) {
        int n = t / 10, rest = t % 10;
        int ee = rest >> 1, iscol = rest & 1;
        const float* wa = Wa + ee*2*Dd + iscol*Dd;
        const float* ms = smsg + n*320 + ee*64;
        float s = 0.f;
#pragma unroll 8
        for (int ff = 0; ff < Dd; ff++) s += ms[ff] * wa[ff];
        int gi = (b*Nn + n0 + n)*Ee + ee;
        if (iscol) g_col[gi] = s; else g_row[gi] = s;
    }
}

// ---------------------------------------------------------------------------
// k2: scores (sigmoid, streamed to out) + partial merged GEMM over one j-split.
// grid 128 (b x 4 j-splits of 32), 256 threads. thread tile 4i x 8d, f32x2.
// ---------------------------------------------------------------------------
__global__ void k2(int titer, const int* __restrict__ mask,
                   const float* __restrict__ ba, float* __restrict__ out) {
    extern __shared__ float sm[];
    float* smsg  = sm;                   // [32][320]   10240
    float* ssc   = smsg + 32*320;        // [128][161]  20608 (padded: kills bank conflicts)
    float* srow  = ssc + 128*161;        // [128][5]
    float* scol  = srow + 640;           // [32][5]
    float* smask = scol + 160;           // [128][32]
    __shared__ float sba[Ee];

    int b   = blockIdx.x >> 2;
    int js  = blockIdx.x & 3;
    int j0  = js * JT;
    int tid = threadIdx.x;

    if (tid < Ee) sba[tid] = ba[tid];
    {
        const float4* gm = (const float4*)(g_msg + (size_t)(b*Nn + j0)*320);
        for (int idx = tid; idx < JT*320/4; idx += 256) ((float4*)smsg)[idx] = gm[idx];
    }
    for (int idx = tid; idx < Nn*Ee; idx += 256) srow[idx] = g_row[b*Nn*Ee + idx];
    for (int idx = tid; idx < JT*Ee; idx += 256) scol[idx] = g_col[(b*Nn + j0)*Ee + idx];
    for (int idx = tid; idx < Nn*JT; idx += 256) {
        int i = idx >> 5, j = idx & 31;
        smask[idx] = (float)mask[(size_t)(b*Nn + i)*Nn + j0 + j];
    }
    __syncthreads();

    // scores: compute once, stage to smem, stream to out
    float* outB = out + ((size_t)titer*Bb + b)*Nn*Nn*Ee;
    for (int idx = tid; idx < Nn*JT*Ee; idx += 256) {
        int i = idx / (JT*Ee);
        int r = idx - i*(JT*Ee);
        int j = r / Ee;
        int e = r - j*Ee;
        float x = srow[i*Ee+e] + scol[j*Ee+e] + sba[e];
        float s = fast_sigmoid(x) * smask[i*JT + j];
        ssc[i*161 + j*Ee + e] = s;
        outB[(size_t)i*Nn*Ee + (size_t)(j0 + j)*Ee + e] = s;
    }
    __syncthreads();

    // merged partial: [128 i][64 d] over k = 32j x 5e
    int td = tid & 7;         // d-group: d = td*8
    int ti = tid >> 3;        // i-group: i = ti*4 + q
    int d0 = td * 8;
    u64 acc[4][4];
#pragma unroll
    for (int q = 0; q < 4; q++)
#pragma unroll
        for (int h = 0; h < 4; h++) acc[q][h] = 0ull;

#pragma unroll 2
    for (int j = 0; j < JT; j++) {
#pragma unroll
        for (int e = 0; e < Ee; e++) {
            const float* mrow = smsg + j*320 + e*64 + d0;
            float4 ma = *(const float4*)mrow;
            float4 mb = *(const float4*)(mrow + 4);
            u64 m0 = pack2(ma.x, ma.y), m1 = pack2(ma.z, ma.w);
            u64 m2 = pack2(mb.x, mb.y), m3 = pack2(mb.z, mb.w);
            const float* sc = ssc + ti*4*161 + j*Ee + e;
#pragma unroll
            for (int q = 0; q < 4; q++) {
                float s = sc[q*161];
                u64 ss = pack2(s, s);
                acc[q][0] = fma2(ss, m0, acc[q][0]);
                acc[q][1] = fma2(ss, m1, acc[q][1]);
                acc[q][2] = fma2(ss, m2, acc[q][2]);
                acc[q][3] = fma2(ss, m3, acc[q][3]);
            }
        }
    }
#pragma unroll
    for (int q = 0; q < 4; q++) {
        int i = ti*4 + q;
        float4 v0, v1;
        unpack2(acc[q][0], v0.x, v0.y);
        unpack2(acc[q][1], v0.z, v0.w);
        unpack2(acc[q][2], v1.x, v1.y);
        unpack2(acc[q][3], v1.z, v1.w);
        *(float4*)&g_part[js][b*Nn + i][d0]     = v0;
        *(float4*)&g_part[js][b*Nn + i][d0 + 4] = v1;
    }
}

// ---------------------------------------------------------------------------
// k_gru: merged = sum of 4 partials; GRU update -> g_prop.
// grid 128 (32 rows each), 256 threads, thread tile 2 rows x 4d, f32x2.
// ---------------------------------------------------------------------------
__global__ void k_gru(const float* __restrict__ prop_ext,
                      const float* __restrict__ Wr, const float* __restrict__ br,
                      const float* __restrict__ Wz, const float* __restrict__ bz,
                      const float* __restrict__ Wh, const float* __restrict__ bh) {
    __shared__ float sa[32][128];   // [merged | prop]
    __shared__ float sh2[32][64];   // r * prop
    const float* prop = prop_ext ? prop_ext : g_prop;
    int r0 = blockIdx.x * 32;
    int tid = threadIdx.x;

    for (int idx = tid; idx < 32*64; idx += 256) {
        int rr = idx >> 6, dd = idx & 63;
        int row = r0 + rr;
        float m = g_part[0][row][dd] + g_part[1][row][dd]
                + g_part[2][row][dd] + g_part[3][row][dd];
        sa[rr][dd]      = m;
        sa[rr][64 + dd] = prop[(size_t)row*Dd + dd];
    }
    __syncthreads();

    int td = tid & 15, tr = tid >> 4;   // rows tr*2 + {0,1}
    int d0 = td * 4;
    float4 brv = *(const float4*)&br[d0];
    float4 bzv = *(const float4*)&bz[d0];
    u64 accr[2][2], accz[2][2];
#pragma unroll
    for (int q = 0; q < 2; q++) {
        accr[q][0] = pack2(brv.x, brv.y); accr[q][1] = pack2(brv.z, brv.w);
        accz[q][0] = pack2(bzv.x, bzv.y); accz[q][1] = pack2(bzv.z, bzv.w);
    }
#pragma unroll 4
    for (int k = 0; k < 128; k++) {
        float4 wr = *(const float4*)&Wr[k*Dd + d0];
        float4 wz = *(const float4*)&Wz[k*Dd + d0];
        u64 wr01 = pack2(wr.x, wr.y), wr23 = pack2(wr.z, wr.w);
        u64 wz01 = pack2(wz.x, wz.y), wz23 = pack2(wz.z, wz.w);
#pragma unroll
        for (int q = 0; q < 2; q++) {
            float a = sa[tr*2+q][k];
            u64 aa = pack2(a, a);
            accr[q][0] = fma2(aa, wr01, accr[q][0]);
            accr[q][1] = fma2(aa, wr23, accr[q][1]);
            accz[q][0] = fma2(aa, wz01, accz[q][0]);
            accz[q][1] = fma2(aa, wz23, accz[q][1]);
        }
    }
    float zq[2][4];
#pragma unroll
    for (int q = 0; q < 2; q++) {
        float rv[4], zv[4];
        unpack2(accr[q][0], rv[0], rv[1]); unpack2(accr[q][1], rv[2], rv[3]);
        unpack2(accz[q][0], zv[0], zv[1]); unpack2(accz[q][1], zv[2], zv[3]);
#pragma unroll
        for (int u = 0; u < 4; u++) {
            float rg = fast_sigmoid(rv[u]);
            zq[q][u] = fast_sigmoid(zv[u]);
            sh2[tr*2+q][d0+u] = rg * sa[tr*2+q][64 + d0 + u];
        }
    }
    __syncthreads();

    float4 bhv = *(const float4*)&bh[d0];
    u64 acch[2][2];
#pragma unroll
    for (int q = 0; q < 2; q++) {
        acch[q][0] = pack2(bhv.x, bhv.y);
        acch[q][1] = pack2(bhv.z, bhv.w);
    }
#pragma unroll 4
    for (int k = 0; k < 64; k++) {
        float4 wh = *(const float4*)&Wh[k*Dd + d0];
        u64 w01 = pack2(wh.x, wh.y), w23 = pack2(wh.z, wh.w);
#pragma unroll
        for (int q = 0; q < 2; q++) {
            float a = sa[tr*2+q][k];
            u64 aa = pack2(a, a);
            acch[q][0] = fma2(aa, w01, acch[q][0]);
            acch[q][1] = fma2(aa, w23, acch[q][1]);
        }
    }
#pragma unroll 4
    for (int k = 0; k < 64; k++) {
        float4 wh = *(const float4*)&Wh[(64+k)*Dd + d0];
        u64 w01 = pack2(wh.x, wh.y), w23 = pack2(wh.z, wh.w);
#pragma unroll
        for (int q = 0; q < 2; q++) {
            float a = sh2[tr*2+q][k];
            u64 aa = pack2(a, a);
            acch[q][0] = fma2(aa, w01, acch[q][0]);
            acch[q][1] = fma2(aa, w23, acch[q][1]);
        }
    }
#pragma unroll
    for (int q = 0; q < 2; q++) {
        float h[4];
        unpack2(acch[q][0], h[0], h[1]);
        unpack2(acch[q][1], h[2], h[3]);
        int row = r0 + tr*2 + q;
        const float* pv = &sa[tr*2+q][64 + d0];
        float4 o;
        o.x = (1.f - zq[q][0])*pv[0] + zq[q][0]*fast_tanh(h[0]);
        o.y = (1.f - zq[q][1])*pv[1] + zq[q][1]*fast_tanh(h[1]);
        o.z = (1.f - zq[q][2])*pv[2] + zq[q][2]*fast_tanh(h[2]);
        o.w = (1.f - zq[q][3])*pv[3] + zq[q][3]*fast_tanh(h[3]);
        *(float4*)&g_prop[(size_t)row*Dd + d0] = o;
    }
}

// ---------------------------------------------------------------------------
extern "C" void kernel_launch(void* const* d_in, const int* in_sizes, int n_in,
                              void* d_out, int out_size) {
    const float* inputs = (const float*)d_in[0];
    const int*   mask   = (const int*)  d_in[1];
    const float* We     = (const float*)d_in[2];
    const float* be     = (const float*)d_in[3];
    const float* Wa     = (const float*)d_in[4];
    const float* ba     = (const float*)d_in[5];
    const float* Wr     = (const float*)d_in[6];
    const float* br     = (const float*)d_in[7];
    const float* Wz     = (const float*)d_in[8];
    const float* bz     = (const float*)d_in[9];
    const float* Wh     = (const float*)d_in[10];
    const float* bh     = (const float*)d_in[11];
    float* out = (float*)d_out;

    const int SMEM_MSG = (32*64 + 32*320) * 4;                       // 48 KB
    const int SMEM_K2  = (32*320 + 128*161 + 640 + 160 + 128*32)*4;  // ~139.6 KB
    cudaFuncSetAttribute(k_msg, cudaFuncAttributeMaxDynamicSharedMemorySize, SMEM_MSG);
    cudaFuncSetAttribute(k2,    cudaFuncAttributeMaxDynamicSharedMemorySize, SMEM_K2);

    for (int t = 0; t < T_ITERS; t++) {
        const float* prop_src = (t == 0) ? inputs : nullptr;
        k_msg<<<Bb*4, 640, SMEM_MSG>>>(prop_src, We, be, Wa);
        k2<<<Bb*JS, 256, SMEM_K2>>>(t, mask, ba, out);
        if (t != T_ITERS - 1)
            k_gru<<<Bb*4, 256>>>(prop_src, Wr, br, Wz, bz, Wh, bh);
    }
}